// round 11
// baseline (speedup 1.0000x reference)
#include <cuda_runtime.h>
#include <cuda_fp16.h>
#include <math.h>
#include <stdint.h>

#define NN   50000
#define EE   400000
#define FIN  128
#define HID  64
#define HEADS 4
#define NCLS 121
#define M1   256
#define M3   484
#define NPAD 50048
#define P1   512   // L1 fp32 out pitch: [xh(256) | lin(256)]
#define P3   616   // L3 fp32 out pitch: [xh(484) | lin(121) | as(4) | ad(4)]
#define P3H  488   // L3 fp16 out pitch (16B-aligned rows)

// ---------------- scratch ----------------
__device__ float  g_xh [(size_t)NN * P3];
__device__ __half g_xh16[(size_t)NN * P3H];
__device__ float  g_h  [(size_t)NN * M1];
__device__ float  g_as [NN * HEADS];
__device__ float  g_ad [NN * HEADS];
__device__ float  g_wext[256 * 8];
__device__ __half g_Ah[(size_t)NPAD * 512];
__device__ __half g_Bt[(size_t)640 * 512];
__device__ int    g_deg   [NN];
__device__ int    g_rowptr[NN + 1];
__device__ int    g_cursor[NN];
__device__ int    g_csrsrc[EE];
__device__ float  g_alpha [(size_t)EE * HEADS];

// ---------------- conversions ----------------
__global__ void convA(const float* __restrict__ X, __half* __restrict__ Ap, int Nrows, int K) {
    long i = blockIdx.x * (long)blockDim.x + threadIdx.x;
    long tot = (long)Nrows * K;
    long stride = (long)gridDim.x * blockDim.x;
    for (; i < tot; i += stride) {
        int r = (int)(i / K), k = (int)(i - (long)r * K);
        float x = X[i];
        __half h = __float2half_rn(x);
        __half l = __float2half_rn(x - __half2float(h));
        __half* row = Ap + (size_t)r * (2 * K);
        row[k] = h; row[K + k] = l;
    }
}
__global__ void convB_W2(const float* __restrict__ W, __half* __restrict__ Bp) {
    int i = blockIdx.x * blockDim.x + threadIdx.x;
    if (i >= 256 * 256) return;
    int n = i >> 8, k = i & 255;
    __half h = __float2half_rn(W[(size_t)k * 256 + n]);
    __half* row = Bp + (size_t)n * 512;
    row[k] = h; row[256 + k] = h;
}
__global__ void convB_L1(const float* __restrict__ W1, const float* __restrict__ linW,
                         __half* __restrict__ Bp) {
    int i = blockIdx.x * blockDim.x + threadIdx.x;
    if (i >= 512 * 128) return;
    int n = i >> 7, k = i & 127;
    float w = (n < 256) ? W1[(size_t)k * 256 + n] : linW[(size_t)k * 256 + (n - 256)];
    __half h = __float2half_rn(w);
    __half* row = Bp + (size_t)n * 256;
    row[k] = h; row[128 + k] = h;
}
__global__ void wext_k(const float* __restrict__ W3, const float* __restrict__ a3s,
                       const float* __restrict__ a3d, float* __restrict__ wext) {
    int t = blockIdx.x * blockDim.x + threadIdx.x;
    if (t >= 256 * 8) return;
    int k = t >> 3, j = t & 7;
    int h = j & 3;
    const float* av = ((j >= 4) ? a3d : a3s) + h * NCLS;
    const float* wr = W3 + (size_t)k * M3 + h * NCLS;
    float s = 0.f;
    for (int c = 0; c < NCLS; c++) s += wr[c] * av[c];
    wext[k * 8 + j] = s;
}
__global__ void convB_L3(const float* __restrict__ W3, const float* __restrict__ linW,
                         const float* __restrict__ wext, __half* __restrict__ Bp) {
    int i = blockIdx.x * blockDim.x + threadIdx.x;
    if (i >= 640 * 256) return;
    int n = i >> 8, k = i & 255;
    float w = 0.f;
    if (n < 484)      w = W3[(size_t)k * M3 + n];
    else if (n < 605) w = linW[(size_t)k * NCLS + (n - 484)];
    else if (n < 613) w = wext[k * 8 + (n - 605)];
    __half h = __float2half_rn(w);
    __half* row = Bp + (size_t)n * 512;
    row[k] = h; row[256 + k] = h;
}

// ---------------- pipelined HMMA fp16 GEMM, fp32 + fp16 dual output ----------------
#define PITCH 80
#define STAGE_BYTES (128 * PITCH)
__global__ __launch_bounds__(256) void gemm_mma(const __half* __restrict__ A,
                                                const __half* __restrict__ Bt,
                                                float* __restrict__ C,
                                                __half* __restrict__ C16,
                                                int Nrows, int Kp, int Nout, int ldc,
                                                int Nout16, int ldc16) {
    __shared__ __align__(16) uint8_t smem[4 * STAGE_BYTES];
    uint32_t sbase = (uint32_t)__cvta_generic_to_shared(smem);
    int tid  = threadIdx.x;
    int wid  = tid >> 5, lane = tid & 31;
    int wm   = wid & 1, wn = wid >> 1;
    int g    = lane >> 2, tg = lane & 3;
    int rowBase = blockIdx.y * 128;
    int colBase = blockIdx.x * 128;
    int lrow = (lane & 7) + ((lane >> 3) & 1) * 8;
    int lcol = (lane >> 4) * 16;

    float acc[4][4][4];
#pragma unroll
    for (int i = 0; i < 4; i++)
#pragma unroll
        for (int j = 0; j < 4; j++)
#pragma unroll
            for (int q = 0; q < 4; q++) acc[i][j][q] = 0.f;

    int isB = tid >> 7;
    int lr  = tid & 127;
    const __half* gsrc = isB ? (Bt + (size_t)(colBase + lr) * Kp)
                             : (A  + (size_t)(rowBase + lr) * Kp);
    int niter = Kp >> 5;
    {
        uint32_t dst = sbase + (uint32_t)isB * STAGE_BYTES + lr * PITCH;
        const uint8_t* src = (const uint8_t*)(gsrc);
#pragma unroll
        for (int c = 0; c < 4; c++)
            asm volatile("cp.async.cg.shared.global [%0], [%1], 16;"
                         :: "r"(dst + c * 16), "l"(src + c * 16) : "memory");
        asm volatile("cp.async.commit_group;" ::: "memory");
    }
    for (int it = 0; it < niter; it++) {
        if (it + 1 < niter) {
            uint32_t dst = sbase + ((it + 1) & 1) * 2 * STAGE_BYTES + (uint32_t)isB * STAGE_BYTES + lr * PITCH;
            const uint8_t* src = (const uint8_t*)(gsrc + (it + 1) * 32);
#pragma unroll
            for (int c = 0; c < 4; c++)
                asm volatile("cp.async.cg.shared.global [%0], [%1], 16;"
                             :: "r"(dst + c * 16), "l"(src + c * 16) : "memory");
            asm volatile("cp.async.commit_group;" ::: "memory");
            asm volatile("cp.async.wait_group 1;" ::: "memory");
        } else {
            asm volatile("cp.async.wait_group 0;" ::: "memory");
        }
        __syncthreads();
        uint32_t sA = sbase + (it & 1) * 2 * STAGE_BYTES;
        uint32_t sB = sA + STAGE_BYTES;
#pragma unroll
        for (int ks = 0; ks < 2; ks++) {
            int kbyte = ks * 32;
            uint32_t a[4][4], b[2][4];
#pragma unroll
            for (int i = 0; i < 4; i++) {
                uint32_t addr = sA + (wm * 64 + i * 16 + lrow) * PITCH + kbyte + lcol;
                asm volatile("ldmatrix.sync.aligned.m8n8.x4.shared.b16 {%0,%1,%2,%3}, [%4];"
                             : "=r"(a[i][0]), "=r"(a[i][1]), "=r"(a[i][2]), "=r"(a[i][3]) : "r"(addr));
            }
#pragma unroll
            for (int p = 0; p < 2; p++) {
                uint32_t addr = sB + (wn * 32 + p * 16 + lrow) * PITCH + kbyte + lcol;
                asm volatile("ldmatrix.sync.aligned.m8n8.x4.shared.b16 {%0,%1,%2,%3}, [%4];"
                             : "=r"(b[p][0]), "=r"(b[p][1]), "=r"(b[p][2]), "=r"(b[p][3]) : "r"(addr));
            }
#pragma unroll
            for (int i = 0; i < 4; i++)
#pragma unroll
                for (int j = 0; j < 4; j++) {
                    uint32_t b0 = b[j >> 1][j & 1];
                    uint32_t b1 = b[j >> 1][2 + (j & 1)];
                    asm volatile(
                        "mma.sync.aligned.m16n8k16.row.col.f32.f16.f16.f32 "
                        "{%0,%1,%2,%3}, {%4,%5,%6,%7}, {%8,%9}, {%0,%1,%2,%3};"
                        : "+f"(acc[i][j][0]), "+f"(acc[i][j][1]), "+f"(acc[i][j][2]), "+f"(acc[i][j][3])
                        : "r"(a[i][0]), "r"(a[i][1]), "r"(a[i][2]), "r"(a[i][3]),
                          "r"(b0), "r"(b1));
                }
        }
        __syncthreads();
    }
#pragma unroll
    for (int i = 0; i < 4; i++) {
        int r0 = rowBase + wm * 64 + i * 16 + g;
#pragma unroll
        for (int j = 0; j < 4; j++) {
            int c0 = colBase + wn * 32 + j * 8 + tg * 2;
#pragma unroll
            for (int rr = 0; rr < 2; rr++) {
                int r = r0 + rr * 8;
                if (r >= Nrows) continue;
                float v0 = acc[i][j][rr * 2], v1 = acc[i][j][rr * 2 + 1];
                if (c0     < Nout) C[(size_t)r * ldc + c0]     = v0;
                if (c0 + 1 < Nout) C[(size_t)r * ldc + c0 + 1] = v1;
                if (c0 + 1 < Nout16) {
                    *(__half2*)(C16 + (size_t)r * ldc16 + c0) = __floats2half2_rn(v0, v1);
                } else if (c0 < Nout16) {
                    C16[(size_t)r * ldc16 + c0] = __float2half_rn(v0);
                }
            }
        }
    }
}

// ---------------- CSR construction ----------------
__global__ void zero_i(int* p, int n) {
    int i = blockIdx.x * blockDim.x + threadIdx.x;
    if (i < n) p[i] = 0;
}
__global__ void hist_dst(const int* __restrict__ ei, int* __restrict__ deg) {
    int e = blockIdx.x * blockDim.x + threadIdx.x;
    if (e < EE) atomicAdd(&deg[ei[EE + e]], 1);
}
__global__ void scan_deg(const int* __restrict__ deg, int* __restrict__ rowptr, int* __restrict__ cursor) {
    __shared__ int part[512];
    int t = threadIdx.x;
    const int CH = (NN + 511) / 512;
    int start = t * CH;
    int s = 0;
    for (int i = 0; i < CH; i++) {
        int idx = start + i;
        if (idx < NN) s += deg[idx];
    }
    part[t] = s;
    __syncthreads();
    for (int off = 1; off < 512; off <<= 1) {
        int v = (t >= off) ? part[t - off] : 0;
        __syncthreads();
        part[t] += v;
        __syncthreads();
    }
    int base = (t == 0) ? 0 : part[t - 1];
    for (int i = 0; i < CH; i++) {
        int idx = start + i;
        if (idx < NN) {
            rowptr[idx] = base;
            cursor[idx] = base;
            base += deg[idx];
        }
    }
    if (t == 511) rowptr[NN] = part[511];
}
__global__ void scatter_csr(const int* __restrict__ ei, int* __restrict__ cursor,
                            int* __restrict__ csrsrc) {
    int e = blockIdx.x * blockDim.x + threadIdx.x;
    if (e >= EE) return;
    int dst = ei[EE + e];
    int p = atomicAdd(&cursor[dst], 1);
    csrsrc[p] = ei[e];
}

// ---------------- alpha (layers 1,2) ----------------
__global__ void alpha_kernel(const float* __restrict__ xh, int pitch,
                             const float* __restrict__ asrc,
                             const float* __restrict__ adst,
                             float* __restrict__ as_, float* __restrict__ ad_,
                             int H, int C) {
    int w    = (blockIdx.x * blockDim.x + threadIdx.x) >> 5;
    int lane = threadIdx.x & 31;
    if (w >= NN * H) return;
    int n = w / H, h = w - n * H;
    const float* row = xh + (size_t)n * pitch + h * C;
    const float* w1  = asrc + h * C;
    const float* w2  = adst + h * C;
    float s1 = 0.f, s2 = 0.f;
    for (int c = lane; c < C; c += 32) {
        float v = row[c];
        s1 += v * w1[c];
        s2 += v * w2[c];
    }
#pragma unroll
    for (int o = 16; o; o >>= 1) {
        s1 += __shfl_down_sync(0xffffffffu, s1, o);
        s2 += __shfl_down_sync(0xffffffffu, s2, o);
    }
    if (lane == 0) { as_[w] = s1; ad_[w] = s2; }
}

// ---------------- softmax (unchanged) ----------------
__global__ void softmax_csr(const int* __restrict__ rowptr, const int* __restrict__ csrsrc,
                            const float* __restrict__ AS, const float* __restrict__ AD,
                            int pitch, float* __restrict__ alpha) {
    int w    = (blockIdx.x * blockDim.x + threadIdx.x) >> 5;
    int lane = threadIdx.x & 31;
    if (w >= NN) return;
    int h  = lane >> 3;
    int j0 = lane & 7;
    int beg = rowptr[w], end = rowptr[w + 1];
    float adv = AD[(size_t)w * pitch + h];
    float m = -INFINITY;
    for (int i = beg + j0; i < end; i += 8) {
        float lg = AS[(size_t)csrsrc[i] * pitch + h] + adv;
        lg = lg > 0.f ? lg : 0.2f * lg;
        alpha[(size_t)i * HEADS + h] = lg;
        m = fmaxf(m, lg);
    }
#pragma unroll
    for (int o = 1; o < 8; o <<= 1) m = fmaxf(m, __shfl_xor_sync(0xffffffffu, m, o));
    float den = 0.f;
    for (int i = beg + j0; i < end; i += 8)
        den += expf(alpha[(size_t)i * HEADS + h] - m);
#pragma unroll
    for (int o = 1; o < 8; o <<= 1) den += __shfl_xor_sync(0xffffffffu, den, o);
    float inv = 1.f / (den + 1e-16f);
    for (int i = beg + j0; i < end; i += 8)
        alpha[(size_t)i * HEADS + h] = expf(alpha[(size_t)i * HEADS + h] - m) * inv;
}

// ---------------- fp16 half8 aggregation ----------------
__device__ __forceinline__ void acc8(float acc[8], float a, uint4 x) {
    __half2* hp = (__half2*)&x;
#pragma unroll
    for (int q = 0; q < 4; q++) {
        float2 f = __half22float2(hp[q]);
        acc[2 * q]     += a * f.x;
        acc[2 * q + 1] += a * f.y;
    }
}

// L1/L2: warp per node, lane = 8 channels. Block 128 = 4 nodes.
__global__ __launch_bounds__(128) void agg_final1(
        const int* __restrict__ rowptr, const int* __restrict__ csrsrc,
        const float* __restrict__ alpha, const __half* __restrict__ xh16,
        const float* __restrict__ xh,
        const float* __restrict__ b1, const float* __restrict__ lin1b,
        float* __restrict__ h_out, __half* __restrict__ Ap) {
    int warp = threadIdx.x >> 5, lane = threadIdx.x & 31;
    int n = blockIdx.x * 4 + warp;
    int cb = lane * 8;
    int h = lane >> 3;
    int beg = rowptr[n], end = rowptr[n + 1];
    float acc[8] = {0, 0, 0, 0, 0, 0, 0, 0};
    int i = beg;
    for (; i + 3 < end; i += 4) {
        int s0 = csrsrc[i], s1 = csrsrc[i + 1], s2 = csrsrc[i + 2], s3 = csrsrc[i + 3];
        float a0 = alpha[(size_t)i * HEADS + h];
        float a1 = alpha[(size_t)(i + 1) * HEADS + h];
        float a2 = alpha[(size_t)(i + 2) * HEADS + h];
        float a3 = alpha[(size_t)(i + 3) * HEADS + h];
        uint4 x0 = *(const uint4*)(xh16 + (size_t)s0 * 256 + cb);
        uint4 x1 = *(const uint4*)(xh16 + (size_t)s1 * 256 + cb);
        uint4 x2 = *(const uint4*)(xh16 + (size_t)s2 * 256 + cb);
        uint4 x3 = *(const uint4*)(xh16 + (size_t)s3 * 256 + cb);
        acc8(acc, a0, x0); acc8(acc, a1, x1); acc8(acc, a2, x2); acc8(acc, a3, x3);
    }
    for (; i < end; i++) {
        float a = alpha[(size_t)i * HEADS + h];
        uint4 x = *(const uint4*)(xh16 + (size_t)csrsrc[i] * 256 + cb);
        acc8(acc, a, x);
    }
    const float* skip = xh + (size_t)n * P1 + 256 + cb;
    float* ho = h_out + (size_t)n * M1 + cb;
    __half* row = Ap + (size_t)n * 512 + cb;
#pragma unroll
    for (int u = 0; u < 8; u++) {
        float v = acc[u] + b1[cb + u] + skip[u] + lin1b[cb + u];
        v = v > 0.f ? v : expm1f(v);
        ho[u] = v;
        __half hi = __float2half_rn(v);
        row[u] = hi;
        row[256 + u] = __float2half_rn(v - __half2float(hi));
    }
}

__global__ __launch_bounds__(128) void agg_final2(
        const int* __restrict__ rowptr, const int* __restrict__ csrsrc,
        const float* __restrict__ alpha, const __half* __restrict__ xh16,
        const float* __restrict__ b2,
        float* __restrict__ h_io, __half* __restrict__ Ap) {
    int warp = threadIdx.x >> 5, lane = threadIdx.x & 31;
    int n = blockIdx.x * 4 + warp;
    int cb = lane * 8;
    int h = lane >> 3;
    int beg = rowptr[n], end = rowptr[n + 1];
    float acc[8] = {0, 0, 0, 0, 0, 0, 0, 0};
    int i = beg;
    for (; i + 3 < end; i += 4) {
        int s0 = csrsrc[i], s1 = csrsrc[i + 1], s2 = csrsrc[i + 2], s3 = csrsrc[i + 3];
        float a0 = alpha[(size_t)i * HEADS + h];
        float a1 = alpha[(size_t)(i + 1) * HEADS + h];
        float a2 = alpha[(size_t)(i + 2) * HEADS + h];
        float a3 = alpha[(size_t)(i + 3) * HEADS + h];
        uint4 x0 = *(const uint4*)(xh16 + (size_t)s0 * 256 + cb);
        uint4 x1 = *(const uint4*)(xh16 + (size_t)s1 * 256 + cb);
        uint4 x2 = *(const uint4*)(xh16 + (size_t)s2 * 256 + cb);
        uint4 x3 = *(const uint4*)(xh16 + (size_t)s3 * 256 + cb);
        acc8(acc, a0, x0); acc8(acc, a1, x1); acc8(acc, a2, x2); acc8(acc, a3, x3);
    }
    for (; i < end; i++) {
        float a = alpha[(size_t)i * HEADS + h];
        uint4 x = *(const uint4*)(xh16 + (size_t)csrsrc[i] * 256 + cb);
        acc8(acc, a, x);
    }
    float* hp = h_io + (size_t)n * M1 + cb;
    __half* row = Ap + (size_t)n * 512 + cb;
#pragma unroll
    for (int u = 0; u < 8; u++) {
        float v = acc[u] + b2[cb + u] + hp[u];
        v = v > 0.f ? v : expm1f(v);
        hp[u] = v;
        __half hi = __float2half_rn(v);
        row[u] = hi;
        row[256 + u] = __float2half_rn(v - __half2float(hi));
    }
}

__device__ __forceinline__ float sel4(float4 av, int h) {
    return h == 0 ? av.x : (h == 1 ? av.y : (h == 2 ? av.z : av.w));
}

// L3: 64 threads per node (61 active), block 128 = 2 nodes.
__global__ __launch_bounds__(128) void agg_final3(
        const int* __restrict__ rowptr, const int* __restrict__ csrsrc,
        const float* __restrict__ alpha, const __half* __restrict__ xh16,
        const float* __restrict__ xh,
        const float* __restrict__ b3, const float* __restrict__ lin3b,
        float* __restrict__ out) {
    __shared__ float sm[2][M3];
    int half = threadIdx.x >> 6;
    int t = threadIdx.x & 63;
    int n = blockIdx.x * 2 + half;
    int cb = t * 8;
    if (cb < M3) {
        int hu[8];
#pragma unroll
        for (int u = 0; u < 8; u++) hu[u] = (cb + u < M3) ? (cb + u) / NCLS : 3;
        int beg = rowptr[n], end = rowptr[n + 1];
        float acc[8] = {0, 0, 0, 0, 0, 0, 0, 0};
        int i = beg;
        for (; i + 1 < end; i += 2) {
            float4 av0 = *(const float4*)(alpha + (size_t)i * HEADS);
            float4 av1 = *(const float4*)(alpha + (size_t)(i + 1) * HEADS);
            uint4 x0 = *(const uint4*)(xh16 + (size_t)csrsrc[i] * P3H + cb);
            uint4 x1 = *(const uint4*)(xh16 + (size_t)csrsrc[i + 1] * P3H + cb);
            __half2* hp0 = (__half2*)&x0;
            __half2* hp1 = (__half2*)&x1;
#pragma unroll
            for (int q = 0; q < 4; q++) {
                float2 f0 = __half22float2(hp0[q]);
                float2 f1 = __half22float2(hp1[q]);
                acc[2 * q]     += sel4(av0, hu[2 * q]) * f0.x + sel4(av1, hu[2 * q]) * f1.x;
                acc[2 * q + 1] += sel4(av0, hu[2 * q + 1]) * f0.y + sel4(av1, hu[2 * q + 1]) * f1.y;
            }
        }
        for (; i < end; i++) {
            float4 av = *(const float4*)(alpha + (size_t)i * HEADS);
            uint4 x = *(const uint4*)(xh16 + (size_t)csrsrc[i] * P3H + cb);
            __half2* hp = (__half2*)&x;
#pragma unroll
            for (int q = 0; q < 4; q++) {
                float2 f = __half22float2(hp[q]);
                acc[2 * q]     += sel4(av, hu[2 * q]) * f.x;
                acc[2 * q + 1] += sel4(av, hu[2 * q + 1]) * f.y;
            }
        }
#pragma unroll
        for (int u = 0; u < 8; u++)
            if (cb + u < M3) sm[half][cb + u] = acc[u];
    }
    __syncthreads();
#pragma unroll
    for (int k = 0; k < 2; k++) {
        int c = t + k * 64;
        if (c < NCLS) {
            float s = 0.25f * (sm[half][c] + sm[half][NCLS + c] + sm[half][2 * NCLS + c] + sm[half][3 * NCLS + c]);
            out[(size_t)n * NCLS + c] = s + b3[c] + xh[(size_t)n * P3 + 484 + c] + lin3b[c];
        }
    }
}

// ---------------- host ----------------
static void launch_gemm(const __half* Ap, const __half* Bp, float* C, __half* C16,
                        int Nrows, int Kp, int Nout, int ldc, int Nout16, int ldc16) {
    dim3 gg((Nout + 127) / 128, (Nrows + 127) / 128);
    gemm_mma<<<gg, 256>>>(Ap, Bp, C, C16, Nrows, Kp, Nout, ldc, Nout16, ldc16);
}

extern "C" void kernel_launch(void* const* d_in, const int* in_sizes, int n_in,
                              void* d_out, int out_size) {
    const float* x      = (const float*)d_in[0];
    const int*   ei     = (const int*)  d_in[1];
    const float* W1     = (const float*)d_in[2];
    const float* a1s    = (const float*)d_in[3];
    const float* a1d    = (const float*)d_in[4];
    const float* b1     = (const float*)d_in[5];
    const float* lin1W  = (const float*)d_in[6];
    const float* lin1b  = (const float*)d_in[7];
    const float* W2     = (const float*)d_in[8];
    const float* a2s    = (const float*)d_in[9];
    const float* a2d    = (const float*)d_in[10];
    const float* b2     = (const float*)d_in[11];
    const float* W3     = (const float*)d_in[12];
    const float* a3s    = (const float*)d_in[13];
    const float* a3d    = (const float*)d_in[14];
    const float* b3     = (const float*)d_in[15];
    const float* lin3W  = (const float*)d_in[16];
    const float* lin3b  = (const float*)d_in[17];
    float* out = (float*)d_out;

    float *xh, *h, *as_, *ad_, *alpha, *wext;
    __half *Ah, *Bt, *xh16;
    int *deg, *rowptr, *cursor, *csrsrc;
    cudaGetSymbolAddress((void**)&xh,  g_xh);
    cudaGetSymbolAddress((void**)&xh16, g_xh16);
    cudaGetSymbolAddress((void**)&h,   g_h);
    cudaGetSymbolAddress((void**)&as_, g_as);
    cudaGetSymbolAddress((void**)&ad_, g_ad);
    cudaGetSymbolAddress((void**)&alpha, g_alpha);
    cudaGetSymbolAddress((void**)&wext, g_wext);
    cudaGetSymbolAddress((void**)&Ah,  g_Ah);
    cudaGetSymbolAddress((void**)&Bt,  g_Bt);
    cudaGetSymbolAddress((void**)&deg,    g_deg);
    cudaGetSymbolAddress((void**)&rowptr, g_rowptr);
    cudaGetSymbolAddress((void**)&cursor, g_cursor);
    cudaGetSymbolAddress((void**)&csrsrc, g_csrsrc);

    // ---- CSR build ----
    zero_i<<<(NN + 255) / 256, 256>>>(deg, NN);
    hist_dst<<<(EE + 255) / 256, 256>>>(ei, deg);
    scan_deg<<<1, 512>>>(deg, rowptr, cursor);
    scatter_csr<<<(EE + 255) / 256, 256>>>(ei, cursor, csrsrc);

    // ---- layer 1 ----
    convA<<<2048, 256>>>(x, Ah, NN, FIN);
    convB_L1<<<(512 * 128 + 255) / 256, 256>>>(W1, lin1W, Bt);
    launch_gemm(Ah, Bt, xh, xh16, NN, 256, 512, P1, 256, 256);
    alpha_kernel<<<(NN * HEADS * 32 + 255) / 256, 256>>>(xh, P1, a1s, a1d, as_, ad_, HEADS, HID);
    softmax_csr<<<(NN * 32 + 255) / 256, 256>>>(rowptr, csrsrc, as_, ad_, HEADS, alpha);
    agg_final1<<<NN / 4, 128>>>(rowptr, csrsrc, alpha, xh16, xh, b1, lin1b, h, Ah);

    // ---- layer 2 ----
    convB_W2<<<(256 * 256 + 255) / 256, 256>>>(W2, Bt);
    launch_gemm(Ah, Bt, xh, xh16, NN, 512, 256, 256, 256, 256);
    alpha_kernel<<<(NN * HEADS * 32 + 255) / 256, 256>>>(xh, 256, a2s, a2d, as_, ad_, HEADS, HID);
    softmax_csr<<<(NN * 32 + 255) / 256, 256>>>(rowptr, csrsrc, as_, ad_, HEADS, alpha);
    agg_final2<<<NN / 4, 128>>>(rowptr, csrsrc, alpha, xh16, b2, h, Ah);

    // ---- layer 3 ----
    wext_k<<<(256 * 8 + 255) / 256, 256>>>(W3, a3s, a3d, wext);
    convB_L3<<<(640 * 256 + 255) / 256, 256>>>(W3, lin3W, wext, Bt);
    launch_gemm(Ah, Bt, xh, xh16, NN, 512, 613, P3, 488, P3H);
    softmax_csr<<<(NN * 32 + 255) / 256, 256>>>(rowptr, csrsrc, xh + 605, xh + 609, P3, alpha);
    agg_final3<<<NN / 2, 128>>>(rowptr, csrsrc, alpha, xh16, xh, b3, lin3b, out);

    (void)in_sizes; (void)n_in; (void)out_size;
}

// round 12
// speedup vs baseline: 1.1461x; 1.1461x over previous
#include <cuda_runtime.h>
#include <cuda_fp16.h>
#include <math.h>
#include <stdint.h>

#define NN   50000
#define EE   400000
#define FIN  128
#define HID  64
#define HEADS 4
#define NCLS 121
#define M1   256
#define M3   484
#define NPAD 50048
#define P1   520   // L1 fp32 out pitch: [xh(256) | lin(256) | as(4) | ad(4)]
#define P2   264   // L2 fp32 out pitch: [xh(256) | as(4) | ad(4)]
#define P3   616   // L3 fp32 out pitch: [xh(484) | lin(121) | as(4) | ad(4)]

// ---------------- scratch ----------------
__device__ float  g_xh [(size_t)NN * P3];
__device__ float  g_h  [(size_t)NN * M1];
__device__ float  g_wext[256 * 8];
__device__ __half g_Ah[(size_t)NPAD * 512];
__device__ __half g_Bt[(size_t)640 * 512];
__device__ int    g_deg   [NN];
__device__ int    g_rowptr[NN + 1];
__device__ int    g_cursor[NN];
__device__ int    g_csrsrc[EE];
__device__ float  g_alpha [(size_t)EE * HEADS];

// ---------------- conversions ----------------
__global__ void convA(const float* __restrict__ X, __half* __restrict__ Ap, int Nrows, int K) {
    long i = blockIdx.x * (long)blockDim.x + threadIdx.x;
    long tot = (long)Nrows * K;
    long stride = (long)gridDim.x * blockDim.x;
    for (; i < tot; i += stride) {
        int r = (int)(i / K), k = (int)(i - (long)r * K);
        float x = X[i];
        __half h = __float2half_rn(x);
        __half l = __float2half_rn(x - __half2float(h));
        __half* row = Ap + (size_t)r * (2 * K);
        row[k] = h; row[K + k] = l;
    }
}
// generic alpha-projection columns: wext[k*8+j] = dot(W[k, h*C : h*C+C], a_{src|dst}[h])
__global__ void wext_g(const float* __restrict__ W, const float* __restrict__ avs,
                       const float* __restrict__ avd, float* __restrict__ wext,
                       int K, int ldw, int C) {
    int t = blockIdx.x * blockDim.x + threadIdx.x;
    if (t >= K * 8) return;
    int k = t >> 3, j = t & 7;
    int h = j & 3;
    const float* av = ((j >= 4) ? avd : avs) + h * C;
    const float* wr = W + (size_t)k * ldw + h * C;
    float s = 0.f;
    for (int c = 0; c < C; c++) s += wr[c] * av[c];
    wext[k * 8 + j] = s;
}
// L1 B': 520 rows x K=128 (pitch 256 halves): [W1(256) | lin1W(256) | wext(8)]
__global__ void convB_L1(const float* __restrict__ W1, const float* __restrict__ linW,
                         const float* __restrict__ wext, __half* __restrict__ Bp) {
    int i = blockIdx.x * blockDim.x + threadIdx.x;
    if (i >= 520 * 128) return;
    int n = i >> 7, k = i & 127;
    float w;
    if (n < 256)      w = W1[(size_t)k * 256 + n];
    else if (n < 512) w = linW[(size_t)k * 256 + (n - 256)];
    else              w = wext[k * 8 + (n - 512)];
    __half h = __float2half_rn(w);
    __half* row = Bp + (size_t)n * 256;
    row[k] = h; row[128 + k] = h;
}
// L2 B': 264 rows x K=256 (pitch 512 halves): [W2(256) | wext(8)]
__global__ void convB_W2(const float* __restrict__ W, const float* __restrict__ wext,
                         __half* __restrict__ Bp) {
    int i = blockIdx.x * blockDim.x + threadIdx.x;
    if (i >= 264 * 256) return;
    int n = i >> 8, k = i & 255;
    float w = (n < 256) ? W[(size_t)k * 256 + n] : wext[k * 8 + (n - 256)];
    __half h = __float2half_rn(w);
    __half* row = Bp + (size_t)n * 512;
    row[k] = h; row[256 + k] = h;
}
// L3 B': 640 rows x K=256 (pitch 512 halves): [W3(484) | lin3W(121) | wext(8) | pad]
__global__ void convB_L3(const float* __restrict__ W3, const float* __restrict__ linW,
                         const float* __restrict__ wext, __half* __restrict__ Bp) {
    int i = blockIdx.x * blockDim.x + threadIdx.x;
    if (i >= 640 * 256) return;
    int n = i >> 8, k = i & 255;
    float w = 0.f;
    if (n < 484)      w = W3[(size_t)k * M3 + n];
    else if (n < 605) w = linW[(size_t)k * NCLS + (n - 484)];
    else if (n < 613) w = wext[k * 8 + (n - 605)];
    __half h = __float2half_rn(w);
    __half* row = Bp + (size_t)n * 512;
    row[k] = h; row[256 + k] = h;
}

// ---------------- pipelined HMMA fp16 GEMM (R9 version, fp32 output) ----------------
#define PITCH 80
#define STAGE_BYTES (128 * PITCH)
__global__ __launch_bounds__(256) void gemm_mma(const __half* __restrict__ A,
                                                const __half* __restrict__ Bt,
                                                float* __restrict__ C,
                                                int Nrows, int Kp, int Nout, int ldc) {
    __shared__ __align__(16) uint8_t smem[4 * STAGE_BYTES];
    uint32_t sbase = (uint32_t)__cvta_generic_to_shared(smem);
    int tid  = threadIdx.x;
    int wid  = tid >> 5, lane = tid & 31;
    int wm   = wid & 1, wn = wid >> 1;
    int g    = lane >> 2, tg = lane & 3;
    int rowBase = blockIdx.y * 128;
    int colBase = blockIdx.x * 128;
    int lrow = (lane & 7) + ((lane >> 3) & 1) * 8;
    int lcol = (lane >> 4) * 16;

    float acc[4][4][4];
#pragma unroll
    for (int i = 0; i < 4; i++)
#pragma unroll
        for (int j = 0; j < 4; j++)
#pragma unroll
            for (int q = 0; q < 4; q++) acc[i][j][q] = 0.f;

    int isB = tid >> 7;
    int lr  = tid & 127;
    const __half* gsrc = isB ? (Bt + (size_t)(colBase + lr) * Kp)
                             : (A  + (size_t)(rowBase + lr) * Kp);
    int niter = Kp >> 5;
    {
        uint32_t dst = sbase + (uint32_t)isB * STAGE_BYTES + lr * PITCH;
        const uint8_t* src = (const uint8_t*)(gsrc);
#pragma unroll
        for (int c = 0; c < 4; c++)
            asm volatile("cp.async.cg.shared.global [%0], [%1], 16;"
                         :: "r"(dst + c * 16), "l"(src + c * 16) : "memory");
        asm volatile("cp.async.commit_group;" ::: "memory");
    }
    for (int it = 0; it < niter; it++) {
        if (it + 1 < niter) {
            uint32_t dst = sbase + ((it + 1) & 1) * 2 * STAGE_BYTES + (uint32_t)isB * STAGE_BYTES + lr * PITCH;
            const uint8_t* src = (const uint8_t*)(gsrc + (it + 1) * 32);
#pragma unroll
            for (int c = 0; c < 4; c++)
                asm volatile("cp.async.cg.shared.global [%0], [%1], 16;"
                             :: "r"(dst + c * 16), "l"(src + c * 16) : "memory");
            asm volatile("cp.async.commit_group;" ::: "memory");
            asm volatile("cp.async.wait_group 1;" ::: "memory");
        } else {
            asm volatile("cp.async.wait_group 0;" ::: "memory");
        }
        __syncthreads();
        uint32_t sA = sbase + (it & 1) * 2 * STAGE_BYTES;
        uint32_t sB = sA + STAGE_BYTES;
#pragma unroll
        for (int ks = 0; ks < 2; ks++) {
            int kbyte = ks * 32;
            uint32_t a[4][4], b[2][4];
#pragma unroll
            for (int i = 0; i < 4; i++) {
                uint32_t addr = sA + (wm * 64 + i * 16 + lrow) * PITCH + kbyte + lcol;
                asm volatile("ldmatrix.sync.aligned.m8n8.x4.shared.b16 {%0,%1,%2,%3}, [%4];"
                             : "=r"(a[i][0]), "=r"(a[i][1]), "=r"(a[i][2]), "=r"(a[i][3]) : "r"(addr));
            }
#pragma unroll
            for (int p = 0; p < 2; p++) {
                uint32_t addr = sB + (wn * 32 + p * 16 + lrow) * PITCH + kbyte + lcol;
                asm volatile("ldmatrix.sync.aligned.m8n8.x4.shared.b16 {%0,%1,%2,%3}, [%4];"
                             : "=r"(b[p][0]), "=r"(b[p][1]), "=r"(b[p][2]), "=r"(b[p][3]) : "r"(addr));
            }
#pragma unroll
            for (int i = 0; i < 4; i++)
#pragma unroll
                for (int j = 0; j < 4; j++) {
                    uint32_t b0 = b[j >> 1][j & 1];
                    uint32_t b1 = b[j >> 1][2 + (j & 1)];
                    asm volatile(
                        "mma.sync.aligned.m16n8k16.row.col.f32.f16.f16.f32 "
                        "{%0,%1,%2,%3}, {%4,%5,%6,%7}, {%8,%9}, {%0,%1,%2,%3};"
                        : "+f"(acc[i][j][0]), "+f"(acc[i][j][1]), "+f"(acc[i][j][2]), "+f"(acc[i][j][3])
                        : "r"(a[i][0]), "r"(a[i][1]), "r"(a[i][2]), "r"(a[i][3]),
                          "r"(b0), "r"(b1));
                }
        }
        __syncthreads();
    }
#pragma unroll
    for (int i = 0; i < 4; i++) {
        int r0 = rowBase + wm * 64 + i * 16 + g;
#pragma unroll
        for (int j = 0; j < 4; j++) {
            int c0 = colBase + wn * 32 + j * 8 + tg * 2;
            if (r0 < Nrows) {
                if (c0     < Nout) C[(size_t)r0 * ldc + c0]     = acc[i][j][0];
                if (c0 + 1 < Nout) C[(size_t)r0 * ldc + c0 + 1] = acc[i][j][1];
            }
            if (r0 + 8 < Nrows) {
                if (c0     < Nout) C[(size_t)(r0 + 8) * ldc + c0]     = acc[i][j][2];
                if (c0 + 1 < Nout) C[(size_t)(r0 + 8) * ldc + c0 + 1] = acc[i][j][3];
            }
        }
    }
}

// ---------------- CSR construction ----------------
__global__ void zero_i(int* p, int n) {
    int i = blockIdx.x * blockDim.x + threadIdx.x;
    if (i < n) p[i] = 0;
}
__global__ void hist_dst(const int* __restrict__ ei, int* __restrict__ deg) {
    int e = blockIdx.x * blockDim.x + threadIdx.x;
    if (e < EE) atomicAdd(&deg[ei[EE + e]], 1);
}
__global__ void scan_deg(const int* __restrict__ deg, int* __restrict__ rowptr, int* __restrict__ cursor) {
    __shared__ int part[512];
    int t = threadIdx.x;
    const int CH = (NN + 511) / 512;
    int start = t * CH;
    int s = 0;
    for (int i = 0; i < CH; i++) {
        int idx = start + i;
        if (idx < NN) s += deg[idx];
    }
    part[t] = s;
    __syncthreads();
    for (int off = 1; off < 512; off <<= 1) {
        int v = (t >= off) ? part[t - off] : 0;
        __syncthreads();
        part[t] += v;
        __syncthreads();
    }
    int base = (t == 0) ? 0 : part[t - 1];
    for (int i = 0; i < CH; i++) {
        int idx = start + i;
        if (idx < NN) {
            rowptr[idx] = base;
            cursor[idx] = base;
            base += deg[idx];
        }
    }
    if (t == 511) rowptr[NN] = part[511];
}
__global__ void scatter_csr(const int* __restrict__ ei, int* __restrict__ cursor,
                            int* __restrict__ csrsrc) {
    int e = blockIdx.x * blockDim.x + threadIdx.x;
    if (e >= EE) return;
    int dst = ei[EE + e];
    int p = atomicAdd(&cursor[dst], 1);
    csrsrc[p] = ei[e];
}

// ---------------- softmax (logit caching) ----------------
__global__ void softmax_csr(const int* __restrict__ rowptr, const int* __restrict__ csrsrc,
                            const float* __restrict__ AS, const float* __restrict__ AD,
                            int pitch, float* __restrict__ alpha) {
    int w    = (blockIdx.x * blockDim.x + threadIdx.x) >> 5;
    int lane = threadIdx.x & 31;
    if (w >= NN) return;
    int h  = lane >> 3;
    int j0 = lane & 7;
    int beg = rowptr[w], end = rowptr[w + 1];
    float adv = AD[(size_t)w * pitch + h];
    float m = -INFINITY;
    for (int i = beg + j0; i < end; i += 8) {
        float lg = AS[(size_t)csrsrc[i] * pitch + h] + adv;
        lg = lg > 0.f ? lg : 0.2f * lg;
        alpha[(size_t)i * HEADS + h] = lg;
        m = fmaxf(m, lg);
    }
#pragma unroll
    for (int o = 1; o < 8; o <<= 1) m = fmaxf(m, __shfl_xor_sync(0xffffffffu, m, o));
    float den = 0.f;
    for (int i = beg + j0; i < end; i += 8)
        den += expf(alpha[(size_t)i * HEADS + h] - m);
#pragma unroll
    for (int o = 1; o < 8; o <<= 1) den += __shfl_xor_sync(0xffffffffu, den, o);
    float inv = 1.f / (den + 1e-16f);
    for (int i = beg + j0; i < end; i += 8)
        alpha[(size_t)i * HEADS + h] = expf(alpha[(size_t)i * HEADS + h] - m) * inv;
}

// ---------------- float4 aggregation, unroll-8 then 4 then scalar ----------------
__device__ __forceinline__ float4 agg_acc4(const int* __restrict__ rowptr,
                                           const int* __restrict__ csrsrc,
                                           const float* __restrict__ alpha,
                                           const float* __restrict__ xh,
                                           int pitch, int n, int cb, int h) {
    int beg = rowptr[n], end = rowptr[n + 1];
    float4 acc = make_float4(0.f, 0.f, 0.f, 0.f);
    int i = beg;
    for (; i + 7 < end; i += 8) {
        int s[8]; float a[8]; float4 x[8];
#pragma unroll
        for (int u = 0; u < 8; u++) s[u] = csrsrc[i + u];
#pragma unroll
        for (int u = 0; u < 8; u++) a[u] = alpha[(size_t)(i + u) * HEADS + h];
#pragma unroll
        for (int u = 0; u < 8; u++) x[u] = *(const float4*)(xh + (size_t)s[u] * pitch + cb);
#pragma unroll
        for (int u = 0; u < 8; u++) {
            acc.x += a[u] * x[u].x; acc.y += a[u] * x[u].y;
            acc.z += a[u] * x[u].z; acc.w += a[u] * x[u].w;
        }
    }
    for (; i + 3 < end; i += 4) {
        int s0 = csrsrc[i], s1 = csrsrc[i + 1], s2 = csrsrc[i + 2], s3 = csrsrc[i + 3];
        float a0 = alpha[(size_t)i * HEADS + h];
        float a1 = alpha[(size_t)(i + 1) * HEADS + h];
        float a2 = alpha[(size_t)(i + 2) * HEADS + h];
        float a3 = alpha[(size_t)(i + 3) * HEADS + h];
        float4 x0 = *(const float4*)(xh + (size_t)s0 * pitch + cb);
        float4 x1 = *(const float4*)(xh + (size_t)s1 * pitch + cb);
        float4 x2 = *(const float4*)(xh + (size_t)s2 * pitch + cb);
        float4 x3 = *(const float4*)(xh + (size_t)s3 * pitch + cb);
        acc.x += a0 * x0.x + a1 * x1.x + a2 * x2.x + a3 * x3.x;
        acc.y += a0 * x0.y + a1 * x1.y + a2 * x2.y + a3 * x3.y;
        acc.z += a0 * x0.z + a1 * x1.z + a2 * x2.z + a3 * x3.z;
        acc.w += a0 * x0.w + a1 * x1.w + a2 * x2.w + a3 * x3.w;
    }
    for (; i < end; i++) {
        float a = alpha[(size_t)i * HEADS + h];
        float4 x = *(const float4*)(xh + (size_t)csrsrc[i] * pitch + cb);
        acc.x += a * x.x; acc.y += a * x.y; acc.z += a * x.z; acc.w += a * x.w;
    }
    return acc;
}
// L3: channels may cross head boundary
__device__ __forceinline__ float4 agg_acc4_mh(const int* __restrict__ rowptr,
                                              const int* __restrict__ csrsrc,
                                              const float* __restrict__ alpha,
                                              const float* __restrict__ xh,
                                              int pitch, int n, int cb,
                                              int h0, int h1, int h2, int h3) {
    int beg = rowptr[n], end = rowptr[n + 1];
    float4 acc = make_float4(0.f, 0.f, 0.f, 0.f);
    for (int i = beg; i < end; i++) {
        float4 av = *(const float4*)(alpha + (size_t)i * HEADS);
        const float* ap = (const float*)&av;
        float4 x = *(const float4*)(xh + (size_t)csrsrc[i] * pitch + cb);
        acc.x += ap[h0] * x.x; acc.y += ap[h1] * x.y;
        acc.z += ap[h2] * x.z; acc.w += ap[h3] * x.w;
    }
    return acc;
}

__global__ __launch_bounds__(64) void agg_final1(
        const int* __restrict__ rowptr, const int* __restrict__ csrsrc,
        const float* __restrict__ alpha, const float* __restrict__ xh,
        const float* __restrict__ b1, const float* __restrict__ lin1b,
        float* __restrict__ h_out, __half* __restrict__ Ap) {
    int n = blockIdx.x, c4 = threadIdx.x;     // 64 threads x 4 channels
    int cb = c4 * 4;
    float4 acc = agg_acc4(rowptr, csrsrc, alpha, xh, P1, n, cb, cb >> 6);
    float4 skip = *(const float4*)(xh + (size_t)n * P1 + 256 + cb);
    float4 bb   = *(const float4*)(b1 + cb);
    float4 lb   = *(const float4*)(lin1b + cb);
    float v[4] = { acc.x + bb.x + skip.x + lb.x, acc.y + bb.y + skip.y + lb.y,
                   acc.z + bb.z + skip.z + lb.z, acc.w + bb.w + skip.w + lb.w };
    __half* row = Ap + (size_t)n * 512;
    float* ho = h_out + (size_t)n * M1 + cb;
#pragma unroll
    for (int u = 0; u < 4; u++) {
        float t = v[u] > 0.f ? v[u] : expm1f(v[u]);
        ho[u] = t;
        __half hi = __float2half_rn(t);
        row[cb + u] = hi;
        row[256 + cb + u] = __float2half_rn(t - __half2float(hi));
    }
}

__global__ __launch_bounds__(64) void agg_final2(
        const int* __restrict__ rowptr, const int* __restrict__ csrsrc,
        const float* __restrict__ alpha, const float* __restrict__ xh,
        const float* __restrict__ b2,
        float* __restrict__ h_io, __half* __restrict__ Ap) {
    int n = blockIdx.x, c4 = threadIdx.x;
    int cb = c4 * 4;
    float4 acc = agg_acc4(rowptr, csrsrc, alpha, xh, P2, n, cb, cb >> 6);
    float4 bb = *(const float4*)(b2 + cb);
    float* hp = h_io + (size_t)n * M1 + cb;
    float4 hv = *(const float4*)hp;
    float v[4] = { acc.x + bb.x + hv.x, acc.y + bb.y + hv.y,
                   acc.z + bb.z + hv.z, acc.w + bb.w + hv.w };
    __half* row = Ap + (size_t)n * 512;
#pragma unroll
    for (int u = 0; u < 4; u++) {
        float t = v[u] > 0.f ? v[u] : expm1f(v[u]);
        hp[u] = t;
        __half hi = __float2half_rn(t);
        row[cb + u] = hi;
        row[256 + cb + u] = __float2half_rn(t - __half2float(hi));
    }
}

__global__ __launch_bounds__(128) void agg_final3(
        const int* __restrict__ rowptr, const int* __restrict__ csrsrc,
        const float* __restrict__ alpha, const float* __restrict__ xh,
        const float* __restrict__ b3, const float* __restrict__ lin3b,
        float* __restrict__ out) {
    __shared__ float sm[M3];
    int n = blockIdx.x, c4 = threadIdx.x;   // 121 threads x 4 channels
    if (c4 < 121) {
        int cb = c4 * 4;
        int h0 = cb / NCLS, h1 = (cb + 1) / NCLS, h2 = (cb + 2) / NCLS, h3 = (cb + 3) / NCLS;
        float4 acc;
        if (h0 == h3) acc = agg_acc4(rowptr, csrsrc, alpha, xh, P3, n, cb, h0);
        else          acc = agg_acc4_mh(rowptr, csrsrc, alpha, xh, P3, n, cb, h0, h1, h2, h3);
        sm[cb] = acc.x; sm[cb + 1] = acc.y; sm[cb + 2] = acc.z; sm[cb + 3] = acc.w;
    }
    __syncthreads();
    int c = threadIdx.x;
    if (c < NCLS) {
        float s = 0.25f * (sm[c] + sm[NCLS + c] + sm[2 * NCLS + c] + sm[3 * NCLS + c]);
        out[(size_t)n * NCLS + c] = s + b3[c] + xh[(size_t)n * P3 + 484 + c] + lin3b[c];
    }
}

// ---------------- host ----------------
static void launch_gemm(const __half* Ap, const __half* Bp, float* C,
                        int Nrows, int Kp, int Nout, int ldc) {
    dim3 gg((Nout + 127) / 128, (Nrows + 127) / 128);
    gemm_mma<<<gg, 256>>>(Ap, Bp, C, Nrows, Kp, Nout, ldc);
}

extern "C" void kernel_launch(void* const* d_in, const int* in_sizes, int n_in,
                              void* d_out, int out_size) {
    const float* x      = (const float*)d_in[0];
    const int*   ei     = (const int*)  d_in[1];
    const float* W1     = (const float*)d_in[2];
    const float* a1s    = (const float*)d_in[3];
    const float* a1d    = (const float*)d_in[4];
    const float* b1     = (const float*)d_in[5];
    const float* lin1W  = (const float*)d_in[6];
    const float* lin1b  = (const float*)d_in[7];
    const float* W2     = (const float*)d_in[8];
    const float* a2s    = (const float*)d_in[9];
    const float* a2d    = (const float*)d_in[10];
    const float* b2     = (const float*)d_in[11];
    const float* W3     = (const float*)d_in[12];
    const float* a3s    = (const float*)d_in[13];
    const float* a3d    = (const float*)d_in[14];
    const float* b3     = (const float*)d_in[15];
    const float* lin3W  = (const float*)d_in[16];
    const float* lin3b  = (const float*)d_in[17];
    float* out = (float*)d_out;

    float *xh, *h, *alpha, *wext;
    __half *Ah, *Bt;
    int *deg, *rowptr, *cursor, *csrsrc;
    cudaGetSymbolAddress((void**)&xh,  g_xh);
    cudaGetSymbolAddress((void**)&h,   g_h);
    cudaGetSymbolAddress((void**)&alpha, g_alpha);
    cudaGetSymbolAddress((void**)&wext, g_wext);
    cudaGetSymbolAddress((void**)&Ah,  g_Ah);
    cudaGetSymbolAddress((void**)&Bt,  g_Bt);
    cudaGetSymbolAddress((void**)&deg,    g_deg);
    cudaGetSymbolAddress((void**)&rowptr, g_rowptr);
    cudaGetSymbolAddress((void**)&cursor, g_cursor);
    cudaGetSymbolAddress((void**)&csrsrc, g_csrsrc);

    // ---- CSR build ----
    zero_i<<<(NN + 255) / 256, 256>>>(deg, NN);
    hist_dst<<<(EE + 255) / 256, 256>>>(ei, deg);
    scan_deg<<<1, 512>>>(deg, rowptr, cursor);
    scatter_csr<<<(EE + 255) / 256, 256>>>(ei, cursor, csrsrc);

    // ---- layer 1: GEMM outputs [xh | lin | as | ad], no separate alpha kernel ----
    convA<<<2048, 256>>>(x, Ah, NN, FIN);
    wext_g<<<(128 * 8 + 255) / 256, 256>>>(W1, a1s, a1d, wext, 128, 256, HID);
    convB_L1<<<(520 * 128 + 255) / 256, 256>>>(W1, lin1W, wext, Bt);
    launch_gemm(Ah, Bt, xh, NN, 256, 520, P1);
    softmax_csr<<<(NN * 32 + 255) / 256, 256>>>(rowptr, csrsrc, xh + 512, xh + 516, P1, alpha);
    agg_final1<<<NN, 64>>>(rowptr, csrsrc, alpha, xh, b1, lin1b, h, Ah);

    // ---- layer 2: GEMM outputs [xh | as | ad] ----
    wext_g<<<(256 * 8 + 255) / 256, 256>>>(W2, a2s, a2d, wext, 256, 256, HID);
    convB_W2<<<(264 * 256 + 255) / 256, 256>>>(W2, wext, Bt);
    launch_gemm(Ah, Bt, xh, NN, 512, 264, P2);
    softmax_csr<<<(NN * 32 + 255) / 256, 256>>>(rowptr, csrsrc, xh + 256, xh + 260, P2, alpha);
    agg_final2<<<NN, 64>>>(rowptr, csrsrc, alpha, xh, b2, h, Ah);

    // ---- layer 3 ----
    wext_g<<<(256 * 8 + 255) / 256, 256>>>(W3, a3s, a3d, wext, 256, M3, NCLS);
    convB_L3<<<(640 * 256 + 255) / 256, 256>>>(W3, lin3W, wext, Bt);
    launch_gemm(Ah, Bt, xh, NN, 512, 613, P3);
    softmax_csr<<<(NN * 32 + 255) / 256, 256>>>(rowptr, csrsrc, xh + 605, xh + 609, P3, alpha);
    agg_final3<<<NN, 128>>>(rowptr, csrsrc, alpha, xh, b3, lin3b, out);

    (void)in_sizes; (void)n_in; (void)out_size;
}

// round 13
// speedup vs baseline: 1.5344x; 1.3388x over previous
#include <cuda_runtime.h>
#include <cuda_fp16.h>
#include <math.h>
#include <stdint.h>

#define NN   50000
#define EE   400000
#define FIN  128
#define HID  64
#define HEADS 4
#define NCLS 121
#define M1   256
#define M3   484
#define NPAD 50048
#define P1   520   // L1 fp32 out pitch: [xh(256) | lin(256) | as(4) | ad(4)]
#define P2   264   // L2 fp32 out pitch: [xh(256) | as(4) | ad(4)]
#define P3   616   // L3 fp32 out pitch: [xh(484) | lin(121) | as(4) | ad(4)]

// ---------------- scratch ----------------
__device__ float  g_xh [(size_t)NN * P3];
__device__ float  g_h  [(size_t)NN * M1];
__device__ float  g_wext[256 * 8];
__device__ __half g_Ah[(size_t)NPAD * 512];   // pitch 128 (L1 input) / 256 (L2,L3 input)
__device__ __half g_Bt[(size_t)640 * 512];
__device__ int    g_deg   [NN];
__device__ int    g_rowptr[NN + 1];
__device__ int    g_cursor[NN];
__device__ int    g_csrsrc[EE];
__device__ float  g_alpha [(size_t)EE * HEADS];

// ---------------- conversions (single-term fp16) ----------------
__global__ void convA(const float* __restrict__ X, __half* __restrict__ Ap, int Nrows, int K) {
    long i = blockIdx.x * (long)blockDim.x + threadIdx.x;
    long tot = (long)Nrows * K;
    long stride = (long)gridDim.x * blockDim.x;
    for (; i < tot; i += stride)
        Ap[i] = __float2half_rn(X[i]);
}
// alpha-projection columns: wext[k*8+j] = dot(W[k, h*C : h*C+C], a_{src|dst}[h])
__global__ void wext_g(const float* __restrict__ W, const float* __restrict__ avs,
                       const float* __restrict__ avd, float* __restrict__ wext,
                       int K, int ldw, int C) {
    int t = blockIdx.x * blockDim.x + threadIdx.x;
    if (t >= K * 8) return;
    int k = t >> 3, j = t & 7;
    int h = j & 3;
    const float* av = ((j >= 4) ? avd : avs) + h * C;
    const float* wr = W + (size_t)k * ldw + h * C;
    float s = 0.f;
    for (int c = 0; c < C; c++) s += wr[c] * av[c];
    wext[k * 8 + j] = s;
}
// L1 B': 520 rows x K=128 (pitch 128): [W1(256) | lin1W(256) | wext(8)]
__global__ void convB_L1(const float* __restrict__ W1, const float* __restrict__ linW,
                         const float* __restrict__ wext, __half* __restrict__ Bp) {
    int i = blockIdx.x * blockDim.x + threadIdx.x;
    if (i >= 520 * 128) return;
    int n = i >> 7, k = i & 127;
    float w;
    if (n < 256)      w = W1[(size_t)k * 256 + n];
    else if (n < 512) w = linW[(size_t)k * 256 + (n - 256)];
    else              w = wext[k * 8 + (n - 512)];
    Bp[(size_t)n * 128 + k] = __float2half_rn(w);
}
// L2 B': 264 rows x K=256 (pitch 256): [W2(256) | wext(8)]
__global__ void convB_W2(const float* __restrict__ W, const float* __restrict__ wext,
                         __half* __restrict__ Bp) {
    int i = blockIdx.x * blockDim.x + threadIdx.x;
    if (i >= 264 * 256) return;
    int n = i >> 8, k = i & 255;
    float w = (n < 256) ? W[(size_t)k * 256 + n] : wext[k * 8 + (n - 256)];
    Bp[(size_t)n * 256 + k] = __float2half_rn(w);
}
// L3 B': 640 rows x K=256 (pitch 256): [W3(484) | lin3W(121) | wext(8) | pad]
__global__ void convB_L3(const float* __restrict__ W3, const float* __restrict__ linW,
                         const float* __restrict__ wext, __half* __restrict__ Bp) {
    int i = blockIdx.x * blockDim.x + threadIdx.x;
    if (i >= 640 * 256) return;
    int n = i >> 8, k = i & 255;
    float w = 0.f;
    if (n < 484)      w = W3[(size_t)k * M3 + n];
    else if (n < 605) w = linW[(size_t)k * NCLS + (n - 484)];
    else if (n < 613) w = wext[k * 8 + (n - 605)];
    Bp[(size_t)n * 256 + k] = __float2half_rn(w);
}

// ---------------- pipelined HMMA fp16 GEMM (unchanged) ----------------
#define PITCH 80
#define STAGE_BYTES (128 * PITCH)
__global__ __launch_bounds__(256) void gemm_mma(const __half* __restrict__ A,
                                                const __half* __restrict__ Bt,
                                                float* __restrict__ C,
                                                int Nrows, int Kp, int Nout, int ldc) {
    __shared__ __align__(16) uint8_t smem[4 * STAGE_BYTES];
    uint32_t sbase = (uint32_t)__cvta_generic_to_shared(smem);
    int tid  = threadIdx.x;
    int wid  = tid >> 5, lane = tid & 31;
    int wm   = wid & 1, wn = wid >> 1;
    int g    = lane >> 2, tg = lane & 3;
    int rowBase = blockIdx.y * 128;
    int colBase = blockIdx.x * 128;
    int lrow = (lane & 7) + ((lane >> 3) & 1) * 8;
    int lcol = (lane >> 4) * 16;

    float acc[4][4][4];
#pragma unroll
    for (int i = 0; i < 4; i++)
#pragma unroll
        for (int j = 0; j < 4; j++)
#pragma unroll
            for (int q = 0; q < 4; q++) acc[i][j][q] = 0.f;

    int isB = tid >> 7;
    int lr  = tid & 127;
    const __half* gsrc = isB ? (Bt + (size_t)(colBase + lr) * Kp)
                             : (A  + (size_t)(rowBase + lr) * Kp);
    int niter = Kp >> 5;
    {
        uint32_t dst = sbase + (uint32_t)isB * STAGE_BYTES + lr * PITCH;
        const uint8_t* src = (const uint8_t*)(gsrc);
#pragma unroll
        for (int c = 0; c < 4; c++)
            asm volatile("cp.async.cg.shared.global [%0], [%1], 16;"
                         :: "r"(dst + c * 16), "l"(src + c * 16) : "memory");
        asm volatile("cp.async.commit_group;" ::: "memory");
    }
    for (int it = 0; it < niter; it++) {
        if (it + 1 < niter) {
            uint32_t dst = sbase + ((it + 1) & 1) * 2 * STAGE_BYTES + (uint32_t)isB * STAGE_BYTES + lr * PITCH;
            const uint8_t* src = (const uint8_t*)(gsrc + (it + 1) * 32);
#pragma unroll
            for (int c = 0; c < 4; c++)
                asm volatile("cp.async.cg.shared.global [%0], [%1], 16;"
                             :: "r"(dst + c * 16), "l"(src + c * 16) : "memory");
            asm volatile("cp.async.commit_group;" ::: "memory");
            asm volatile("cp.async.wait_group 1;" ::: "memory");
        } else {
            asm volatile("cp.async.wait_group 0;" ::: "memory");
        }
        __syncthreads();
        uint32_t sA = sbase + (it & 1) * 2 * STAGE_BYTES;
        uint32_t sB = sA + STAGE_BYTES;
#pragma unroll
        for (int ks = 0; ks < 2; ks++) {
            int kbyte = ks * 32;
            uint32_t a[4][4], b[2][4];
#pragma unroll
            for (int i = 0; i < 4; i++) {
                uint32_t addr = sA + (wm * 64 + i * 16 + lrow) * PITCH + kbyte + lcol;
                asm volatile("ldmatrix.sync.aligned.m8n8.x4.shared.b16 {%0,%1,%2,%3}, [%4];"
                             : "=r"(a[i][0]), "=r"(a[i][1]), "=r"(a[i][2]), "=r"(a[i][3]) : "r"(addr));
            }
#pragma unroll
            for (int p = 0; p < 2; p++) {
                uint32_t addr = sB + (wn * 32 + p * 16 + lrow) * PITCH + kbyte + lcol;
                asm volatile("ldmatrix.sync.aligned.m8n8.x4.shared.b16 {%0,%1,%2,%3}, [%4];"
                             : "=r"(b[p][0]), "=r"(b[p][1]), "=r"(b[p][2]), "=r"(b[p][3]) : "r"(addr));
            }
#pragma unroll
            for (int i = 0; i < 4; i++)
#pragma unroll
                for (int j = 0; j < 4; j++) {
                    uint32_t b0 = b[j >> 1][j & 1];
                    uint32_t b1 = b[j >> 1][2 + (j & 1)];
                    asm volatile(
                        "mma.sync.aligned.m16n8k16.row.col.f32.f16.f16.f32 "
                        "{%0,%1,%2,%3}, {%4,%5,%6,%7}, {%8,%9}, {%0,%1,%2,%3};"
                        : "+f"(acc[i][j][0]), "+f"(acc[i][j][1]), "+f"(acc[i][j][2]), "+f"(acc[i][j][3])
                        : "r"(a[i][0]), "r"(a[i][1]), "r"(a[i][2]), "r"(a[i][3]),
                          "r"(b0), "r"(b1));
                }
        }
        __syncthreads();
    }
#pragma unroll
    for (int i = 0; i < 4; i++) {
        int r0 = rowBase + wm * 64 + i * 16 + g;
#pragma unroll
        for (int j = 0; j < 4; j++) {
            int c0 = colBase + wn * 32 + j * 8 + tg * 2;
            if (r0 < Nrows) {
                if (c0     < Nout) C[(size_t)r0 * ldc + c0]     = acc[i][j][0];
                if (c0 + 1 < Nout) C[(size_t)r0 * ldc + c0 + 1] = acc[i][j][1];
            }
            if (r0 + 8 < Nrows) {
                if (c0     < Nout) C[(size_t)(r0 + 8) * ldc + c0]     = acc[i][j][2];
                if (c0 + 1 < Nout) C[(size_t)(r0 + 8) * ldc + c0 + 1] = acc[i][j][3];
            }
        }
    }
}

// ---------------- CSR construction ----------------
__global__ void zero_i(int* p, int n) {
    int i = blockIdx.x * blockDim.x + threadIdx.x;
    if (i < n) p[i] = 0;
}
__global__ void hist_dst(const int* __restrict__ ei, int* __restrict__ deg) {
    int e = blockIdx.x * blockDim.x + threadIdx.x;
    if (e < EE) atomicAdd(&deg[ei[EE + e]], 1);
}
__global__ void scan_deg(const int* __restrict__ deg, int* __restrict__ rowptr, int* __restrict__ cursor) {
    __shared__ int part[512];
    int t = threadIdx.x;
    const int CH = (NN + 511) / 512;
    int start = t * CH;
    int s = 0;
    for (int i = 0; i < CH; i++) {
        int idx = start + i;
        if (idx < NN) s += deg[idx];
    }
    part[t] = s;
    __syncthreads();
    for (int off = 1; off < 512; off <<= 1) {
        int v = (t >= off) ? part[t - off] : 0;
        __syncthreads();
        part[t] += v;
        __syncthreads();
    }
    int base = (t == 0) ? 0 : part[t - 1];
    for (int i = 0; i < CH; i++) {
        int idx = start + i;
        if (idx < NN) {
            rowptr[idx] = base;
            cursor[idx] = base;
            base += deg[idx];
        }
    }
    if (t == 511) rowptr[NN] = part[511];
}
__global__ void scatter_csr(const int* __restrict__ ei, int* __restrict__ cursor,
                            int* __restrict__ csrsrc) {
    int e = blockIdx.x * blockDim.x + threadIdx.x;
    if (e >= EE) return;
    int dst = ei[EE + e];
    int p = atomicAdd(&cursor[dst], 1);
    csrsrc[p] = ei[e];
}

// ---------------- softmax (logit caching) ----------------
__global__ void softmax_csr(const int* __restrict__ rowptr, const int* __restrict__ csrsrc,
                            const float* __restrict__ AS, const float* __restrict__ AD,
                            int pitch, float* __restrict__ alpha) {
    int w    = (blockIdx.x * blockDim.x + threadIdx.x) >> 5;
    int lane = threadIdx.x & 31;
    if (w >= NN) return;
    int h  = lane >> 3;
    int j0 = lane & 7;
    int beg = rowptr[w], end = rowptr[w + 1];
    float adv = AD[(size_t)w * pitch + h];
    float m = -INFINITY;
    for (int i = beg + j0; i < end; i += 8) {
        float lg = AS[(size_t)csrsrc[i] * pitch + h] + adv;
        lg = lg > 0.f ? lg : 0.2f * lg;
        alpha[(size_t)i * HEADS + h] = lg;
        m = fmaxf(m, lg);
    }
#pragma unroll
    for (int o = 1; o < 8; o <<= 1) m = fmaxf(m, __shfl_xor_sync(0xffffffffu, m, o));
    float den = 0.f;
    for (int i = beg + j0; i < end; i += 8)
        den += expf(alpha[(size_t)i * HEADS + h] - m);
#pragma unroll
    for (int o = 1; o < 8; o <<= 1) den += __shfl_xor_sync(0xffffffffu, den, o);
    float inv = 1.f / (den + 1e-16f);
    for (int i = beg + j0; i < end; i += 8)
        alpha[(size_t)i * HEADS + h] = expf(alpha[(size_t)i * HEADS + h] - m) * inv;
}

// ---------------- float4 aggregation, unroll-8/4/scalar ----------------
__device__ __forceinline__ float4 agg_acc4(const int* __restrict__ rowptr,
                                           const int* __restrict__ csrsrc,
                                           const float* __restrict__ alpha,
                                           const float* __restrict__ xh,
                                           int pitch, int n, int cb, int h) {
    int beg = rowptr[n], end = rowptr[n + 1];
    float4 acc = make_float4(0.f, 0.f, 0.f, 0.f);
    int i = beg;
    for (; i + 7 < end; i += 8) {
        int s[8]; float a[8]; float4 x[8];
#pragma unroll
        for (int u = 0; u < 8; u++) s[u] = csrsrc[i + u];
#pragma unroll
        for (int u = 0; u < 8; u++) a[u] = alpha[(size_t)(i + u) * HEADS + h];
#pragma unroll
        for (int u = 0; u < 8; u++) x[u] = *(const float4*)(xh + (size_t)s[u] * pitch + cb);
#pragma unroll
        for (int u = 0; u < 8; u++) {
            acc.x += a[u] * x[u].x; acc.y += a[u] * x[u].y;
            acc.z += a[u] * x[u].z; acc.w += a[u] * x[u].w;
        }
    }
    for (; i + 3 < end; i += 4) {
        int s0 = csrsrc[i], s1 = csrsrc[i + 1], s2 = csrsrc[i + 2], s3 = csrsrc[i + 3];
        float a0 = alpha[(size_t)i * HEADS + h];
        float a1 = alpha[(size_t)(i + 1) * HEADS + h];
        float a2 = alpha[(size_t)(i + 2) * HEADS + h];
        float a3 = alpha[(size_t)(i + 3) * HEADS + h];
        float4 x0 = *(const float4*)(xh + (size_t)s0 * pitch + cb);
        float4 x1 = *(const float4*)(xh + (size_t)s1 * pitch + cb);
        float4 x2 = *(const float4*)(xh + (size_t)s2 * pitch + cb);
        float4 x3 = *(const float4*)(xh + (size_t)s3 * pitch + cb);
        acc.x += a0 * x0.x + a1 * x1.x + a2 * x2.x + a3 * x3.x;
        acc.y += a0 * x0.y + a1 * x1.y + a2 * x2.y + a3 * x3.y;
        acc.z += a0 * x0.z + a1 * x1.z + a2 * x2.z + a3 * x3.z;
        acc.w += a0 * x0.w + a1 * x1.w + a2 * x2.w + a3 * x3.w;
    }
    for (; i < end; i++) {
        float a = alpha[(size_t)i * HEADS + h];
        float4 x = *(const float4*)(xh + (size_t)csrsrc[i] * pitch + cb);
        acc.x += a * x.x; acc.y += a * x.y; acc.z += a * x.z; acc.w += a * x.w;
    }
    return acc;
}
__device__ __forceinline__ float4 agg_acc4_mh(const int* __restrict__ rowptr,
                                              const int* __restrict__ csrsrc,
                                              const float* __restrict__ alpha,
                                              const float* __restrict__ xh,
                                              int pitch, int n, int cb,
                                              int h0, int h1, int h2, int h3) {
    int beg = rowptr[n], end = rowptr[n + 1];
    float4 acc = make_float4(0.f, 0.f, 0.f, 0.f);
    for (int i = beg; i < end; i++) {
        float4 av = *(const float4*)(alpha + (size_t)i * HEADS);
        const float* ap = (const float*)&av;
        float4 x = *(const float4*)(xh + (size_t)csrsrc[i] * pitch + cb);
        acc.x += ap[h0] * x.x; acc.y += ap[h1] * x.y;
        acc.z += ap[h2] * x.z; acc.w += ap[h3] * x.w;
    }
    return acc;
}

__global__ __launch_bounds__(64) void agg_final1(
        const int* __restrict__ rowptr, const int* __restrict__ csrsrc,
        const float* __restrict__ alpha, const float* __restrict__ xh,
        const float* __restrict__ b1, const float* __restrict__ lin1b,
        float* __restrict__ h_out, __half* __restrict__ Ap) {
    int n = blockIdx.x, c4 = threadIdx.x;
    int cb = c4 * 4;
    float4 acc = agg_acc4(rowptr, csrsrc, alpha, xh, P1, n, cb, cb >> 6);
    float4 skip = *(const float4*)(xh + (size_t)n * P1 + 256 + cb);
    float4 bb   = *(const float4*)(b1 + cb);
    float4 lb   = *(const float4*)(lin1b + cb);
    float v[4] = { acc.x + bb.x + skip.x + lb.x, acc.y + bb.y + skip.y + lb.y,
                   acc.z + bb.z + skip.z + lb.z, acc.w + bb.w + skip.w + lb.w };
    __half* row = Ap + (size_t)n * 256;
    float* ho = h_out + (size_t)n * M1 + cb;
#pragma unroll
    for (int u = 0; u < 4; u++) {
        float t = v[u] > 0.f ? v[u] : expm1f(v[u]);
        ho[u] = t;
        row[cb + u] = __float2half_rn(t);
    }
}

__global__ __launch_bounds__(64) void agg_final2(
        const int* __restrict__ rowptr, const int* __restrict__ csrsrc,
        const float* __restrict__ alpha, const float* __restrict__ xh,
        const float* __restrict__ b2,
        float* __restrict__ h_io, __half* __restrict__ Ap) {
    int n = blockIdx.x, c4 = threadIdx.x;
    int cb = c4 * 4;
    float4 acc = agg_acc4(rowptr, csrsrc, alpha, xh, P2, n, cb, cb >> 6);
    float4 bb = *(const float4*)(b2 + cb);
    float* hp = h_io + (size_t)n * M1 + cb;
    float4 hv = *(const float4*)hp;
    float v[4] = { acc.x + bb.x + hv.x, acc.y + bb.y + hv.y,
                   acc.z + bb.z + hv.z, acc.w + bb.w + hv.w };
    __half* row = Ap + (size_t)n * 256;
#pragma unroll
    for (int u = 0; u < 4; u++) {
        float t = v[u] > 0.f ? v[u] : expm1f(v[u]);
        hp[u] = t;
        row[cb + u] = __float2half_rn(t);
    }
}

__global__ __launch_bounds__(128) void agg_final3(
        const int* __restrict__ rowptr, const int* __restrict__ csrsrc,
        const float* __restrict__ alpha, const float* __restrict__ xh,
        const float* __restrict__ b3, const float* __restrict__ lin3b,
        float* __restrict__ out) {
    __shared__ float sm[M3];
    int n = blockIdx.x, c4 = threadIdx.x;
    if (c4 < 121) {
        int cb = c4 * 4;
        int h0 = cb / NCLS, h1 = (cb + 1) / NCLS, h2 = (cb + 2) / NCLS, h3 = (cb + 3) / NCLS;
        float4 acc;
        if (h0 == h3) acc = agg_acc4(rowptr, csrsrc, alpha, xh, P3, n, cb, h0);
        else          acc = agg_acc4_mh(rowptr, csrsrc, alpha, xh, P3, n, cb, h0, h1, h2, h3);
        sm[cb] = acc.x; sm[cb + 1] = acc.y; sm[cb + 2] = acc.z; sm[cb + 3] = acc.w;
    }
    __syncthreads();
    int c = threadIdx.x;
    if (c < NCLS) {
        float s = 0.25f * (sm[c] + sm[NCLS + c] + sm[2 * NCLS + c] + sm[3 * NCLS + c]);
        out[(size_t)n * NCLS + c] = s + b3[c] + xh[(size_t)n * P3 + 484 + c] + lin3b[c];
    }
}

// ---------------- host ----------------
static void launch_gemm(const __half* Ap, const __half* Bp, float* C,
                        int Nrows, int Kp, int Nout, int ldc) {
    dim3 gg((Nout + 127) / 128, (Nrows + 127) / 128);
    gemm_mma<<<gg, 256>>>(Ap, Bp, C, Nrows, Kp, Nout, ldc);
}

extern "C" void kernel_launch(void* const* d_in, const int* in_sizes, int n_in,
                              void* d_out, int out_size) {
    const float* x      = (const float*)d_in[0];
    const int*   ei     = (const int*)  d_in[1];
    const float* W1     = (const float*)d_in[2];
    const float* a1s    = (const float*)d_in[3];
    const float* a1d    = (const float*)d_in[4];
    const float* b1     = (const float*)d_in[5];
    const float* lin1W  = (const float*)d_in[6];
    const float* lin1b  = (const float*)d_in[7];
    const float* W2     = (const float*)d_in[8];
    const float* a2s    = (const float*)d_in[9];
    const float* a2d    = (const float*)d_in[10];
    const float* b2     = (const float*)d_in[11];
    const float* W3     = (const float*)d_in[12];
    const float* a3s    = (const float*)d_in[13];
    const float* a3d    = (const float*)d_in[14];
    const float* b3     = (const float*)d_in[15];
    const float* lin3W  = (const float*)d_in[16];
    const float* lin3b  = (const float*)d_in[17];
    float* out = (float*)d_out;

    float *xh, *h, *alpha, *wext;
    __half *Ah, *Bt;
    int *deg, *rowptr, *cursor, *csrsrc;
    cudaGetSymbolAddress((void**)&xh,  g_xh);
    cudaGetSymbolAddress((void**)&h,   g_h);
    cudaGetSymbolAddress((void**)&alpha, g_alpha);
    cudaGetSymbolAddress((void**)&wext, g_wext);
    cudaGetSymbolAddress((void**)&Ah,  g_Ah);
    cudaGetSymbolAddress((void**)&Bt,  g_Bt);
    cudaGetSymbolAddress((void**)&deg,    g_deg);
    cudaGetSymbolAddress((void**)&rowptr, g_rowptr);
    cudaGetSymbolAddress((void**)&cursor, g_cursor);
    cudaGetSymbolAddress((void**)&csrsrc, g_csrsrc);

    // ---- CSR build ----
    zero_i<<<(NN + 255) / 256, 256>>>(deg, NN);
    hist_dst<<<(EE + 255) / 256, 256>>>(ei, deg);
    scan_deg<<<1, 512>>>(deg, rowptr, cursor);
    scatter_csr<<<(EE + 255) / 256, 256>>>(ei, cursor, csrsrc);

    // ---- layer 1: GEMM outputs [xh | lin | as | ad] (K=128) ----
    convA<<<2048, 256>>>(x, Ah, NN, FIN);
    wext_g<<<(128 * 8 + 255) / 256, 256>>>(W1, a1s, a1d, wext, 128, 256, HID);
    convB_L1<<<(520 * 128 + 255) / 256, 256>>>(W1, lin1W, wext, Bt);
    launch_gemm(Ah, Bt, xh, NN, 128, 520, P1);
    softmax_csr<<<(NN * 32 + 255) / 256, 256>>>(rowptr, csrsrc, xh + 512, xh + 516, P1, alpha);
    agg_final1<<<NN, 64>>>(rowptr, csrsrc, alpha, xh, b1, lin1b, h, Ah);

    // ---- layer 2: GEMM outputs [xh | as | ad] (K=256) ----
    wext_g<<<(256 * 8 + 255) / 256, 256>>>(W2, a2s, a2d, wext, 256, 256, HID);
    convB_W2<<<(264 * 256 + 255) / 256, 256>>>(W2, wext, Bt);
    launch_gemm(Ah, Bt, xh, NN, 256, 264, P2);
    softmax_csr<<<(NN * 32 + 255) / 256, 256>>>(rowptr, csrsrc, xh + 256, xh + 260, P2, alpha);
    agg_final2<<<NN, 64>>>(rowptr, csrsrc, alpha, xh, b2, h, Ah);

    // ---- layer 3 (K=256) ----
    wext_g<<<(256 * 8 + 255) / 256, 256>>>(W3, a3s, a3d, wext, 256, M3, NCLS);
    convB_L3<<<(640 * 256 + 255) / 256, 256>>>(W3, lin3W, wext, Bt);
    launch_gemm(Ah, Bt, xh, NN, 256, 613, P3);
    softmax_csr<<<(NN * 32 + 255) / 256, 256>>>(rowptr, csrsrc, xh + 605, xh + 609, P3, alpha);
    agg_final3<<<NN, 128>>>(rowptr, csrsrc, alpha, xh, b3, lin3b, out);

    (void)in_sizes; (void)n_in; (void)out_size;
}